// round 1
// baseline (speedup 1.0000x reference)
#include <cuda_runtime.h>

#define IMG_H 2048
#define IMG_W 2048
#define HW (IMG_H * IMG_W)
#define NCH 3
#define ITER 8

// Ping-pong scratch planes (CHW, planar). Device globals: allowed scratch.
__device__ float g_bufA[NCH * HW];
__device__ float g_bufB[NCH * HW];

// ---------------------------------------------------------------------------
// HWC -> CHW planar
// ---------------------------------------------------------------------------
__global__ void hwc2chw_kernel(const float* __restrict__ img) {
    int p = blockIdx.x * blockDim.x + threadIdx.x;
    if (p >= HW) return;
    float v0 = img[3 * p + 0];
    float v1 = img[3 * p + 1];
    float v2 = img[3 * p + 2];
    g_bufA[0 * HW + p] = v0;
    g_bufA[1 * HW + p] = v1;
    g_bufA[2 * HW + p] = v2;
}

// ---------------------------------------------------------------------------
// One side-window-filter iteration over one channel plane.
// Tile: 32 wide x 32 high, block (32,4), each thread does 8 vertical pixels.
// ---------------------------------------------------------------------------
#define TX 32
#define TY 32
#define PY 8
#define SW_STRIDE (TX + 4)

__global__ __launch_bounds__(128) void swf_step_kernel(int srcIsA) {
    const float* __restrict__ src = (srcIsA ? g_bufA : g_bufB) + blockIdx.z * HW;
    float* __restrict__ dst       = (srcIsA ? g_bufB : g_bufA) + blockIdx.z * HW;

    __shared__ float tile[(TY + 4) * SW_STRIDE];

    const int bx = blockIdx.x * TX;
    const int by = blockIdx.y * TY;
    const int tid = threadIdx.y * 32 + threadIdx.x;

    // Cooperative load of (TY+4) x (TX+4) halo tile with replicate clamping.
    #pragma unroll
    for (int i = tid; i < (TY + 4) * SW_STRIDE; i += 128) {
        int ly = i / SW_STRIDE;
        int lx = i - ly * SW_STRIDE;
        int gy = by + ly - 2;
        int gx = bx + lx - 2;
        gy = min(max(gy, 0), IMG_H - 1);
        gx = min(max(gx, 0), IMG_W - 1);
        tile[i] = src[gy * IMG_W + gx];
    }
    __syncthreads();

    const int lx = threadIdx.x;            // output column within tile
    const int y0 = threadIdx.y * PY;       // first output row within tile

    // Per-row horizontal sums over the 12 rows covering PY outputs + halo.
    float hl[PY + 4], hr[PY + 4], hf[PY + 4], cc[PY + 4];
    #pragma unroll
    for (int r = 0; r < PY + 4; r++) {
        const float* row = &tile[(y0 + r) * SW_STRIDE + lx];
        float v0 = row[0], v1 = row[1], v2 = row[2], v3 = row[3], v4 = row[4];
        float l = v0 + v1 + v2;
        float rr = v2 + v3 + v4;
        hl[r] = l;
        hr[r] = rr;
        hf[r] = l + v3 + v4;
        cc[r] = v2;
    }

    const float w15 = 1.0f / 15.0f;
    const float w9  = 1.0f / 9.0f;

    #pragma unroll
    for (int p = 0; p < PY; p++) {
        // vertical 3-sums: A = rows [c-2..c], B = rows [c..c+2], center idx p+2
        float Al = hl[p] + hl[p + 1] + hl[p + 2];
        float Bl = hl[p + 2] + hl[p + 3] + hl[p + 4];
        float Ar = hr[p] + hr[p + 1] + hr[p + 2];
        float Br = hr[p + 2] + hr[p + 3] + hr[p + 4];
        float Af = hf[p] + hf[p + 1] + hf[p + 2];
        float Bf = hf[p + 2] + hf[p + 3] + hf[p + 4];

        float c = cc[p + 2];

        // conv values in argmin order: L, R, U, D, NW, NE, SW, SE
        float dL  = (Al + Bl - hl[p + 2]) * w15 - c;
        float dR  = (Ar + Br - hr[p + 2]) * w15 - c;
        float dU  = Af * w15 - c;
        float dD  = Bf * w15 - c;
        float dNW = Al * w9 - c;
        float dNE = Ar * w9 - c;
        float dSW = Bl * w9 - c;
        float dSE = Br * w9 - c;

        float bd = dL;
        float ba = fabsf(dL);
        float a;
        a = fabsf(dR);  if (a < ba) { ba = a; bd = dR;  }
        a = fabsf(dU);  if (a < ba) { ba = a; bd = dU;  }
        a = fabsf(dD);  if (a < ba) { ba = a; bd = dD;  }
        a = fabsf(dNW); if (a < ba) { ba = a; bd = dNW; }
        a = fabsf(dNE); if (a < ba) { ba = a; bd = dNE; }
        a = fabsf(dSW); if (a < ba) { ba = a; bd = dSW; }
        a = fabsf(dSE); if (a < ba) { ba = a; bd = dSE; }

        dst[(by + y0 + p) * IMG_W + bx + lx] = c + bd;
    }
}

// ---------------------------------------------------------------------------
// |x0 - res| clipped, CHW -> HWC
// ---------------------------------------------------------------------------
__global__ void finalize_kernel(const float* __restrict__ img, float* __restrict__ out) {
    int p = blockIdx.x * blockDim.x + threadIdx.x;
    if (p >= HW) return;
    #pragma unroll
    for (int ch = 0; ch < NCH; ch++) {
        float d = fabsf(img[3 * p + ch] - g_bufA[ch * HW + p]);
        out[3 * p + ch] = fminf(d, 255.0f);
    }
}

// ---------------------------------------------------------------------------
extern "C" void kernel_launch(void* const* d_in, const int* in_sizes, int n_in,
                              void* d_out, int out_size) {
    const float* img = (const float*)d_in[0];
    float* out = (float*)d_out;

    hwc2chw_kernel<<<HW / 256, 256>>>(img);

    dim3 grid(IMG_W / TX, IMG_H / TY, NCH);
    dim3 block(32, 4);
    for (int it = 0; it < ITER; it++) {
        swf_step_kernel<<<grid, block>>>((it & 1) == 0 ? 1 : 0);
    }
    // After 8 iterations (even), result is back in g_bufA.
    finalize_kernel<<<HW / 256, 256>>>(img, out);
}

// round 2
// speedup vs baseline: 1.3790x; 1.3790x over previous
#include <cuda_runtime.h>

#define IMG_H 2048
#define IMG_W 2048
#define HW (IMG_H * IMG_W)
#define NCH 3
#define ITER 8

// Ping-pong scratch planes (CHW, planar). Device globals: allowed scratch.
__device__ float g_bufA[NCH * HW];
__device__ float g_bufB[NCH * HW];

typedef unsigned long long ull;

// ---------------- packed f32x2 helpers (Blackwell dual-FP32) ----------------
__device__ __forceinline__ ull pk(float lo, float hi) {
    ull r; asm("mov.b64 %0, {%1, %2};" : "=l"(r) : "f"(lo), "f"(hi)); return r;
}
__device__ __forceinline__ void upk(ull v, float& lo, float& hi) {
    asm("mov.b64 {%0, %1}, %2;" : "=f"(lo), "=f"(hi) : "l"(v));
}
__device__ __forceinline__ ull add2(ull a, ull b) {
    ull r; asm("add.rn.f32x2 %0, %1, %2;" : "=l"(r) : "l"(a), "l"(b)); return r;
}
__device__ __forceinline__ ull mul2(ull a, ull b) {
    ull r; asm("mul.rn.f32x2 %0, %1, %2;" : "=l"(r) : "l"(a), "l"(b)); return r;
}
__device__ __forceinline__ ull fma2(ull a, ull b, ull c) {
    ull r; asm("fma.rn.f32x2 %0, %1, %2, %3;" : "=l"(r) : "l"(a), "l"(b), "l"(c)); return r;
}
// keep `a` on tie (earlier kernel has priority) -> FSETP(|.|)+FSEL, 2 ops
__device__ __forceinline__ float selmin(float a, float b) {
    return (fabsf(b) < fabsf(a)) ? b : a;
}

// ---------------------------------------------------------------------------
// HWC -> CHW planar (float4-vectorized, 4 pixels/thread)
// ---------------------------------------------------------------------------
__global__ void hwc2chw_kernel(const float* __restrict__ img) {
    int p = blockIdx.x * blockDim.x + threadIdx.x;
    if (p >= HW / 4) return;
    const float4* in = (const float4*)img + 3 * p;
    float4 a = in[0], b = in[1], c = in[2];
    ((float4*)(g_bufA + 0 * HW))[p] = make_float4(a.x, a.w, b.z, c.y);
    ((float4*)(g_bufA + 1 * HW))[p] = make_float4(a.y, b.x, b.w, c.z);
    ((float4*)(g_bufA + 2 * HW))[p] = make_float4(a.z, b.y, c.x, c.w);
}

// ---------------------------------------------------------------------------
// One SWF iteration. Tile: 64 wide x 32 high per block (32,4)=128 threads.
// Each thread: 2 adjacent columns (packed f32x2) x 8 rows = 16 pixels.
// ---------------------------------------------------------------------------
#define TX 64
#define TY 32
#define STRIDE 68   // 64 + 4 halo, even -> LDS.64 stays 8B aligned

__global__ __launch_bounds__(128) void swf_step_kernel(int srcIsA) {
    const float* __restrict__ src = (srcIsA ? g_bufA : g_bufB) + blockIdx.z * HW;
    float* __restrict__ dst       = (srcIsA ? g_bufB : g_bufA) + blockIdx.z * HW;

    __shared__ float tile[36 * STRIDE];

    const int tx = threadIdx.x, ty = threadIdx.y;
    const int bx = blockIdx.x * TX, by = blockIdx.y * TY;

    const bool interior = (blockIdx.x > 0) && (blockIdx.x < gridDim.x - 1) &&
                          (blockIdx.y > 0) && (blockIdx.y < gridDim.y - 1);

    if (interior) {
        const float* g = src + (by - 2) * IMG_W + (bx - 2);
        #pragma unroll
        for (int r = ty; r < 36; r += 4) {
            *(float2*)&tile[r * STRIDE + 2 * tx] = *(const float2*)(g + r * IMG_W + 2 * tx);
            if (tx < 2) {
                *(float2*)&tile[r * STRIDE + 64 + 2 * tx] =
                    *(const float2*)(g + r * IMG_W + 64 + 2 * tx);
            }
        }
    } else {
        #pragma unroll
        for (int r = ty; r < 36; r += 4) {
            int gy = min(max(by + r - 2, 0), IMG_H - 1);
            const float* grow = src + gy * IMG_W;
            int c0 = min(max(bx + 2 * tx - 2, 0), IMG_W - 1);
            int c1 = min(max(bx + 2 * tx - 1, 0), IMG_W - 1);
            *(float2*)&tile[r * STRIDE + 2 * tx] = make_float2(grow[c0], grow[c1]);
            if (tx < 2) {
                int c2 = min(max(bx + 62 + 2 * tx, 0), IMG_W - 1);
                int c3 = min(max(bx + 63 + 2 * tx, 0), IMG_W - 1);
                *(float2*)&tile[r * STRIDE + 64 + 2 * tx] = make_float2(grow[c2], grow[c3]);
            }
        }
    }
    __syncthreads();

    const int row0 = ty * 8;

    // ring buffers: horizontal left/right 3-sums and center pair, 5 rows live
    ull Hl[5], Hr[5], Cc[5];

    auto loadrow = [&](int r, ull& hl, ull& hr, ull& cc) {
        const float* base = &tile[r * STRIDE + 2 * tx];
        float2 v01 = *(const float2*)(base);
        float2 v23 = *(const float2*)(base + 2);
        float2 v45 = *(const float2*)(base + 4);
        ull A01 = pk(v01.x, v01.y);
        ull A23 = pk(v23.x, v23.y);
        ull A45 = pk(v45.x, v45.y);
        ull A12 = pk(v01.y, v23.x);
        ull A34 = pk(v23.y, v45.x);
        hl = add2(add2(A01, A12), A23);  // cols [x-2..x] per lane
        hr = add2(add2(A23, A34), A45);  // cols [x..x+2] per lane
        cc = A23;                        // center values
    };

    #pragma unroll
    for (int k = 0; k < 4; k++) loadrow(row0 + k, Hl[k], Hr[k], Cc[k]);

    // vertical 3-sum pipeline: V(t) = rows t..t+2.  A(p)=V(p), B(p)=V(p+2)=A(p+2)
    ull VHl[2], VHr[2], VHc[2];
    VHl[0] = add2(add2(Hl[0], Hl[1]), Hl[2]);
    VHr[0] = add2(add2(Hr[0], Hr[1]), Hr[2]);
    VHc[0] = add2(add2(Cc[0], Cc[1]), Cc[2]);
    VHl[1] = add2(add2(Hl[1], Hl[2]), Hl[3]);
    VHr[1] = add2(add2(Hr[1], Hr[2]), Hr[3]);
    VHc[1] = add2(add2(Cc[1], Cc[2]), Cc[3]);

    const ull K9    = 0x4110000041100000ULL;  // ( 9, 9)
    const ull Km9   = 0xC1100000C1100000ULL;  // (-9,-9)
    const ull K15   = 0x4170000041700000ULL;  // (15,15)
    const ull Km135 = 0xC3070000C3070000ULL;  // (-135,-135)
    const float INV135 = 1.0f / 135.0f;

    float* drow = dst + (by + row0) * IMG_W + bx + 2 * tx;

    #pragma unroll
    for (int p = 0; p < 8; p++) {
        const int s4 = (p + 4) % 5;
        loadrow(row0 + p + 4, Hl[s4], Hr[s4], Cc[s4]);
        const int i2 = (p + 2) % 5, i3 = (p + 3) % 5;

        ull Bl = add2(add2(Hl[i2], Hl[i3]), Hl[s4]);
        ull Br = add2(add2(Hr[i2], Hr[i3]), Hr[s4]);
        ull Bc = add2(add2(Cc[i2], Cc[i3]), Cc[s4]);
        ull Al = VHl[p & 1], Ar = VHr[p & 1], Ac = VHc[p & 1];
        VHl[p & 1] = Bl; VHr[p & 1] = Br; VHc[p & 1] = Bc;

        ull cc2  = Cc[i2];
        ull negC = mul2(cc2, Km135);
        ull hlc  = Hl[i2], hrc = Hr[i2];

        // residuals scaled by 135: e = 135*(conv - c); argmin|e| == argmin|d|
        ull eL  = fma2(hlc, Km9, fma2(add2(Al, Bl), K9, negC));
        ull eR  = fma2(hrc, Km9, fma2(add2(Ar, Br), K9, negC));
        ull eU  = fma2(Ac,  Km9, fma2(add2(Al, Ar), K9, negC));
        ull eD  = fma2(Bc,  Km9, fma2(add2(Bl, Br), K9, negC));
        ull eNW = fma2(Al, K15, negC);
        ull eNE = fma2(Ar, K15, negC);
        ull eSW = fma2(Bl, K15, negC);
        ull eSE = fma2(Br, K15, negC);

        float c0, c1;   upk(cc2, c0, c1);
        float l0, l1;   upk(eL,  l0, l1);
        float r0, r1;   upk(eR,  r0, r1);
        float u0, u1;   upk(eU,  u0, u1);
        float d0, d1;   upk(eD,  d0, d1);
        float nw0, nw1; upk(eNW, nw0, nw1);
        float ne0, ne1; upk(eNE, ne0, ne1);
        float sw0, sw1; upk(eSW, sw0, sw1);
        float se0, se1; upk(eSE, se0, se1);

        float m0 = selmin(selmin(selmin(l0, r0), selmin(u0, d0)),
                          selmin(selmin(nw0, ne0), selmin(sw0, se0)));
        float m1 = selmin(selmin(selmin(l1, r1), selmin(u1, d1)),
                          selmin(selmin(nw1, ne1), selmin(sw1, se1)));

        *(float2*)drow = make_float2(fmaf(m0, INV135, c0), fmaf(m1, INV135, c1));
        drow += IMG_W;
    }
}

// ---------------------------------------------------------------------------
// |x0 - res| clipped, CHW -> HWC (float4-vectorized, 4 pixels/thread)
// ---------------------------------------------------------------------------
__global__ void finalize_kernel(const float* __restrict__ img, float* __restrict__ out) {
    int p = blockIdx.x * blockDim.x + threadIdx.x;
    if (p >= HW / 4) return;
    const float4* in = (const float4*)img + 3 * p;
    float4 a = in[0], b = in[1], c = in[2];
    float4 r0 = ((const float4*)(g_bufA + 0 * HW))[p];
    float4 r1 = ((const float4*)(g_bufA + 1 * HW))[p];
    float4 r2 = ((const float4*)(g_bufA + 2 * HW))[p];
    float4 o0 = make_float4(fminf(fabsf(a.x - r0.x), 255.f), fminf(fabsf(a.y - r1.x), 255.f),
                            fminf(fabsf(a.z - r2.x), 255.f), fminf(fabsf(a.w - r0.y), 255.f));
    float4 o1 = make_float4(fminf(fabsf(b.x - r1.y), 255.f), fminf(fabsf(b.y - r2.y), 255.f),
                            fminf(fabsf(b.z - r0.z), 255.f), fminf(fabsf(b.w - r1.z), 255.f));
    float4 o2 = make_float4(fminf(fabsf(c.x - r2.z), 255.f), fminf(fabsf(c.y - r0.w), 255.f),
                            fminf(fabsf(c.z - r1.w), 255.f), fminf(fabsf(c.w - r2.w), 255.f));
    float4* op = (float4*)out + 3 * p;
    op[0] = o0; op[1] = o1; op[2] = o2;
}

// ---------------------------------------------------------------------------
extern "C" void kernel_launch(void* const* d_in, const int* in_sizes, int n_in,
                              void* d_out, int out_size) {
    const float* img = (const float*)d_in[0];
    float* out = (float*)d_out;

    hwc2chw_kernel<<<HW / 4 / 256, 256>>>(img);

    dim3 grid(IMG_W / TX, IMG_H / TY, NCH);
    dim3 block(32, 4);
    for (int it = 0; it < ITER; it++) {
        swf_step_kernel<<<grid, block>>>((it & 1) == 0 ? 1 : 0);
    }
    // After 8 iterations (even), result is back in g_bufA.
    finalize_kernel<<<HW / 4 / 256, 256>>>(img, out);
}

// round 3
// speedup vs baseline: 1.4370x; 1.0421x over previous
#include <cuda_runtime.h>

#define IMG_H 2048
#define IMG_W 2048
#define HW (IMG_H * IMG_W)
#define NCH 3
#define ITER 8

// Ping-pong scratch planes (CHW, planar). Device globals: allowed scratch.
__device__ float g_bufA[NCH * HW];
__device__ float g_bufB[NCH * HW];

typedef unsigned long long ull;

// ---------------- packed f32x2 helpers (Blackwell dual-FP32) ----------------
__device__ __forceinline__ ull pk(float lo, float hi) {
    ull r; asm("mov.b64 %0, {%1, %2};" : "=l"(r) : "f"(lo), "f"(hi)); return r;
}
__device__ __forceinline__ void upk(ull v, float& lo, float& hi) {
    asm("mov.b64 {%0, %1}, %2;" : "=f"(lo), "=f"(hi) : "l"(v));
}
__device__ __forceinline__ ull add2(ull a, ull b) {
    ull r; asm("add.rn.f32x2 %0, %1, %2;" : "=l"(r) : "l"(a), "l"(b)); return r;
}
__device__ __forceinline__ ull mul2(ull a, ull b) {
    ull r; asm("mul.rn.f32x2 %0, %1, %2;" : "=l"(r) : "l"(a), "l"(b)); return r;
}
__device__ __forceinline__ ull fma2(ull a, ull b, ull c) {
    ull r; asm("fma.rn.f32x2 %0, %1, %2, %3;" : "=l"(r) : "l"(a), "l"(b), "l"(c)); return r;
}
// keep `a` on tie (earlier kernel has priority) -> FSETP(|.|)+FSEL, 2 ops
__device__ __forceinline__ float selmin(float a, float b) {
    return (fabsf(b) < fabsf(a)) ? b : a;
}

// ---------------------------------------------------------------------------
// HWC -> CHW planar (float4-vectorized, 4 pixels/thread)
// ---------------------------------------------------------------------------
__global__ void hwc2chw_kernel(const float* __restrict__ img) {
    int p = blockIdx.x * blockDim.x + threadIdx.x;
    if (p >= HW / 4) return;
    const float4* in = (const float4*)img + 3 * p;
    float4 a = in[0], b = in[1], c = in[2];
    ((float4*)(g_bufA + 0 * HW))[p] = make_float4(a.x, a.w, b.z, c.y);
    ((float4*)(g_bufA + 1 * HW))[p] = make_float4(a.y, b.x, b.w, c.z);
    ((float4*)(g_bufA + 2 * HW))[p] = make_float4(a.z, b.y, c.x, c.w);
}

// ---------------------------------------------------------------------------
// One SWF iteration. Tile: 64 wide x 32 high per block (32,4)=128 threads.
// Each thread: 2 adjacent columns (packed f32x2) x 8 rows = 16 pixels.
// ---------------------------------------------------------------------------
#define TX 64
#define TY 32
#define STRIDE 68   // 64 + 4 halo, even -> LDS.64 stays 8B aligned

__global__ __launch_bounds__(128) void swf_step_kernel(int srcIsA) {
    const float* __restrict__ src = (srcIsA ? g_bufA : g_bufB) + blockIdx.z * HW;
    float* __restrict__ dst       = (srcIsA ? g_bufB : g_bufA) + blockIdx.z * HW;

    __shared__ float tile[36 * STRIDE];

    const int tx = threadIdx.x, ty = threadIdx.y;
    const int bx = blockIdx.x * TX, by = blockIdx.y * TY;

    const bool interior = (blockIdx.x > 0) && (blockIdx.x < gridDim.x - 1) &&
                          (blockIdx.y > 0) && (blockIdx.y < gridDim.y - 1);

    if (interior) {
        const float* g = src + (by - 2) * IMG_W + (bx - 2);
        #pragma unroll
        for (int r = ty; r < 36; r += 4) {
            *(float2*)&tile[r * STRIDE + 2 * tx] = *(const float2*)(g + r * IMG_W + 2 * tx);
            if (tx < 2) {
                *(float2*)&tile[r * STRIDE + 64 + 2 * tx] =
                    *(const float2*)(g + r * IMG_W + 64 + 2 * tx);
            }
        }
    } else {
        #pragma unroll
        for (int r = ty; r < 36; r += 4) {
            int gy = min(max(by + r - 2, 0), IMG_H - 1);
            const float* grow = src + gy * IMG_W;
            int c0 = min(max(bx + 2 * tx - 2, 0), IMG_W - 1);
            int c1 = min(max(bx + 2 * tx - 1, 0), IMG_W - 1);
            *(float2*)&tile[r * STRIDE + 2 * tx] = make_float2(grow[c0], grow[c1]);
            if (tx < 2) {
                int c2 = min(max(bx + 62 + 2 * tx, 0), IMG_W - 1);
                int c3 = min(max(bx + 63 + 2 * tx, 0), IMG_W - 1);
                *(float2*)&tile[r * STRIDE + 64 + 2 * tx] = make_float2(grow[c2], grow[c3]);
            }
        }
    }
    __syncthreads();

    const int row0 = ty * 8;

    // ring buffers: horizontal left/right 3-sums and center pair, 5 rows live
    ull Hl[5], Hr[5], Cc[5];

    // Scalar horizontal adds (no cross-pair register shuffles), packed results.
    auto loadrow = [&](int r, ull& hl, ull& hr, ull& cc) {
        const float* base = &tile[r * STRIDE + 2 * tx];
        float2 a = *(const float2*)(base);      // v0 v1
        float2 b = *(const float2*)(base + 2);  // v2 v3 (center pair)
        float2 c = *(const float2*)(base + 4);  // v4 v5
        float t = a.y + b.x;                    // v1+v2
        float u = b.y + c.x;                    // v3+v4
        float hl0 = a.x + t;                    // v0+v1+v2
        float hl1 = t + b.y;                    // v1+v2+v3
        float hr0 = b.x + u;                    // v2+v3+v4
        float hr1 = u + c.y;                    // v3+v4+v5
        hl = pk(hl0, hl1);
        hr = pk(hr0, hr1);
        cc = pk(b.x, b.y);                      // aligned pair straight from LDS.64
    };

    #pragma unroll
    for (int k = 0; k < 4; k++) loadrow(row0 + k, Hl[k], Hr[k], Cc[k]);

    // vertical 3-sum pipeline: V(t) = rows t..t+2.  A(p)=V(p), B(p)=V(p+2)=A(p+2)
    ull VHl[2], VHr[2], VHc[2];
    VHl[0] = add2(add2(Hl[0], Hl[1]), Hl[2]);
    VHr[0] = add2(add2(Hr[0], Hr[1]), Hr[2]);
    VHc[0] = add2(add2(Cc[0], Cc[1]), Cc[2]);
    VHl[1] = add2(add2(Hl[1], Hl[2]), Hl[3]);
    VHr[1] = add2(add2(Hr[1], Hr[2]), Hr[3]);
    VHc[1] = add2(add2(Cc[1], Cc[2]), Cc[3]);

    const ull K9    = 0x4110000041100000ULL;  // ( 9, 9)
    const ull Km9   = 0xC1100000C1100000ULL;  // (-9,-9)
    const ull K15   = 0x4170000041700000ULL;  // (15,15)
    const ull Km135 = 0xC3070000C3070000ULL;  // (-135,-135)
    const float INV135 = 1.0f / 135.0f;

    float* drow = dst + (by + row0) * IMG_W + bx + 2 * tx;

    #pragma unroll
    for (int p = 0; p < 8; p++) {
        const int s4 = (p + 4) % 5;
        loadrow(row0 + p + 4, Hl[s4], Hr[s4], Cc[s4]);
        const int i2 = (p + 2) % 5, i3 = (p + 3) % 5;

        ull Bl = add2(add2(Hl[i2], Hl[i3]), Hl[s4]);
        ull Br = add2(add2(Hr[i2], Hr[i3]), Hr[s4]);
        ull Bc = add2(add2(Cc[i2], Cc[i3]), Cc[s4]);
        ull Al = VHl[p & 1], Ar = VHr[p & 1], Ac = VHc[p & 1];
        VHl[p & 1] = Bl; VHr[p & 1] = Br; VHc[p & 1] = Bc;

        ull cc2  = Cc[i2];
        ull negC = mul2(cc2, Km135);
        ull hlc  = Hl[i2], hrc = Hr[i2];

        // residuals scaled by 135: e = 135*(conv - c); argmin|e| == argmin|d|
        ull eL  = fma2(hlc, Km9, fma2(add2(Al, Bl), K9, negC));
        ull eR  = fma2(hrc, Km9, fma2(add2(Ar, Br), K9, negC));
        ull eU  = fma2(Ac,  Km9, fma2(add2(Al, Ar), K9, negC));
        ull eD  = fma2(Bc,  Km9, fma2(add2(Bl, Br), K9, negC));
        ull eNW = fma2(Al, K15, negC);
        ull eNE = fma2(Ar, K15, negC);
        ull eSW = fma2(Bl, K15, negC);
        ull eSE = fma2(Br, K15, negC);

        float c0, c1;   upk(cc2, c0, c1);
        float l0, l1;   upk(eL,  l0, l1);
        float r0, r1;   upk(eR,  r0, r1);
        float u0, u1;   upk(eU,  u0, u1);
        float d0, d1;   upk(eD,  d0, d1);
        float nw0, nw1; upk(eNW, nw0, nw1);
        float ne0, ne1; upk(eNE, ne0, ne1);
        float sw0, sw1; upk(eSW, sw0, sw1);
        float se0, se1; upk(eSE, se0, se1);

        float m0 = selmin(selmin(selmin(l0, r0), selmin(u0, d0)),
                          selmin(selmin(nw0, ne0), selmin(sw0, se0)));
        float m1 = selmin(selmin(selmin(l1, r1), selmin(u1, d1)),
                          selmin(selmin(nw1, ne1), selmin(sw1, se1)));

        *(float2*)drow = make_float2(fmaf(m0, INV135, c0), fmaf(m1, INV135, c1));
        drow += IMG_W;
    }
}

// ---------------------------------------------------------------------------
// |x0 - res| clipped, CHW -> HWC (float4-vectorized, 4 pixels/thread)
// ---------------------------------------------------------------------------
__global__ void finalize_kernel(const float* __restrict__ img, float* __restrict__ out) {
    int p = blockIdx.x * blockDim.x + threadIdx.x;
    if (p >= HW / 4) return;
    const float4* in = (const float4*)img + 3 * p;
    float4 a = in[0], b = in[1], c = in[2];
    float4 r0 = ((const float4*)(g_bufA + 0 * HW))[p];
    float4 r1 = ((const float4*)(g_bufA + 1 * HW))[p];
    float4 r2 = ((const float4*)(g_bufA + 2 * HW))[p];
    float4 o0 = make_float4(fminf(fabsf(a.x - r0.x), 255.f), fminf(fabsf(a.y - r1.x), 255.f),
                            fminf(fabsf(a.z - r2.x), 255.f), fminf(fabsf(a.w - r0.y), 255.f));
    float4 o1 = make_float4(fminf(fabsf(b.x - r1.y), 255.f), fminf(fabsf(b.y - r2.y), 255.f),
                            fminf(fabsf(b.z - r0.z), 255.f), fminf(fabsf(b.w - r1.z), 255.f));
    float4 o2 = make_float4(fminf(fabsf(c.x - r2.z), 255.f), fminf(fabsf(c.y - r0.w), 255.f),
                            fminf(fabsf(c.z - r1.w), 255.f), fminf(fabsf(c.w - r2.w), 255.f));
    float4* op = (float4*)out + 3 * p;
    op[0] = o0; op[1] = o1; op[2] = o2;
}

// ---------------------------------------------------------------------------
extern "C" void kernel_launch(void* const* d_in, const int* in_sizes, int n_in,
                              void* d_out, int out_size) {
    const float* img = (const float*)d_in[0];
    float* out = (float*)d_out;

    hwc2chw_kernel<<<HW / 4 / 256, 256>>>(img);

    dim3 grid(IMG_W / TX, IMG_H / TY, NCH);
    dim3 block(32, 4);
    for (int it = 0; it < ITER; it++) {
        swf_step_kernel<<<grid, block>>>((it & 1) == 0 ? 1 : 0);
    }
    // After 8 iterations (even), result is back in g_bufA.
    finalize_kernel<<<HW / 4 / 256, 256>>>(img, out);
}

// round 4
// speedup vs baseline: 1.5049x; 1.0472x over previous
#include <cuda_runtime.h>

#define IMG_H 2048
#define IMG_W 2048
#define HW (IMG_H * IMG_W)
#define NCH 3
#define ITER 8

// Ping-pong scratch planes (CHW, planar). Device globals: allowed scratch.
__device__ float g_bufA[NCH * HW];
__device__ float g_bufB[NCH * HW];

typedef unsigned long long ull;

// ---------------- packed f32x2 helpers (Blackwell dual-FP32) ----------------
__device__ __forceinline__ ull pk(float lo, float hi) {
    ull r; asm("mov.b64 %0, {%1, %2};" : "=l"(r) : "f"(lo), "f"(hi)); return r;
}
__device__ __forceinline__ void upk(ull v, float& lo, float& hi) {
    asm("mov.b64 {%0, %1}, %2;" : "=f"(lo), "=f"(hi) : "l"(v));
}
__device__ __forceinline__ ull add2(ull a, ull b) {
    ull r; asm("add.rn.f32x2 %0, %1, %2;" : "=l"(r) : "l"(a), "l"(b)); return r;
}
__device__ __forceinline__ ull mul2(ull a, ull b) {
    ull r; asm("mul.rn.f32x2 %0, %1, %2;" : "=l"(r) : "l"(a), "l"(b)); return r;
}
__device__ __forceinline__ ull fma2(ull a, ull b, ull c) {
    ull r; asm("fma.rn.f32x2 %0, %1, %2, %3;" : "=l"(r) : "l"(a), "l"(b), "l"(c)); return r;
}
// keep `a` on tie (earlier kernel has priority) -> FSETP(|.|)+FSEL, 2 ops
__device__ __forceinline__ float selmin(float a, float b) {
    return (fabsf(b) < fabsf(a)) ? b : a;
}

// ---------------------------------------------------------------------------
// HWC -> CHW planar (float4-vectorized, 4 pixels/thread)
// ---------------------------------------------------------------------------
__global__ void hwc2chw_kernel(const float* __restrict__ img) {
    int p = blockIdx.x * blockDim.x + threadIdx.x;
    if (p >= HW / 4) return;
    const float4* in = (const float4*)img + 3 * p;
    float4 a = in[0], b = in[1], c = in[2];
    ((float4*)(g_bufA + 0 * HW))[p] = make_float4(a.x, a.w, b.z, c.y);
    ((float4*)(g_bufA + 1 * HW))[p] = make_float4(a.y, b.x, b.w, c.z);
    ((float4*)(g_bufA + 2 * HW))[p] = make_float4(a.z, b.y, c.x, c.w);
}

// ---------------------------------------------------------------------------
// One SWF iteration. Tile: 64 wide x 64 high per block (32,4)=128 threads.
// Each thread: 2 adjacent columns (packed f32x2) x 16 rows = 32 pixels.
// ---------------------------------------------------------------------------
#define TX 64
#define TY 64
#define PY 16
#define STRIDE 68   // 64 + 4 halo, even -> LDS.64 stays 8B aligned
#define TROWS (TY + 4)

__global__ __launch_bounds__(128) void swf_step_kernel(int srcIsA) {
    const float* __restrict__ src = (srcIsA ? g_bufA : g_bufB) + blockIdx.z * HW;
    float* __restrict__ dst       = (srcIsA ? g_bufB : g_bufA) + blockIdx.z * HW;

    __shared__ float tile[TROWS * STRIDE];

    const int tx = threadIdx.x, ty = threadIdx.y;
    const int bx = blockIdx.x * TX, by = blockIdx.y * TY;

    const bool interior = (blockIdx.x > 0) && (blockIdx.x < gridDim.x - 1) &&
                          (blockIdx.y > 0) && (blockIdx.y < gridDim.y - 1);

    if (interior) {
        const float* g = src + (by - 2) * IMG_W + (bx - 2);
        #pragma unroll
        for (int r = ty; r < TROWS; r += 4) {
            *(float2*)&tile[r * STRIDE + 2 * tx] = *(const float2*)(g + r * IMG_W + 2 * tx);
            if (tx < 2) {
                *(float2*)&tile[r * STRIDE + 64 + 2 * tx] =
                    *(const float2*)(g + r * IMG_W + 64 + 2 * tx);
            }
        }
    } else {
        #pragma unroll
        for (int r = ty; r < TROWS; r += 4) {
            int gy = min(max(by + r - 2, 0), IMG_H - 1);
            const float* grow = src + gy * IMG_W;
            int c0 = min(max(bx + 2 * tx - 2, 0), IMG_W - 1);
            int c1 = min(max(bx + 2 * tx - 1, 0), IMG_W - 1);
            *(float2*)&tile[r * STRIDE + 2 * tx] = make_float2(grow[c0], grow[c1]);
            if (tx < 2) {
                int c2 = min(max(bx + 62 + 2 * tx, 0), IMG_W - 1);
                int c3 = min(max(bx + 63 + 2 * tx, 0), IMG_W - 1);
                *(float2*)&tile[r * STRIDE + 64 + 2 * tx] = make_float2(grow[c2], grow[c3]);
            }
        }
    }
    __syncthreads();

    const int row0 = ty * PY;

    // ring buffers: horizontal left/right 3-sums and center pair, 5 rows live
    ull Hl[5], Hr[5], Cc[5];

    // Scalar horizontal adds (no cross-pair register shuffles), packed results.
    auto loadrow = [&](int r, ull& hl, ull& hr, ull& cc) {
        const float* base = &tile[r * STRIDE + 2 * tx];
        float2 a = *(const float2*)(base);      // v0 v1
        float2 b = *(const float2*)(base + 2);  // v2 v3 (center pair)
        float2 c = *(const float2*)(base + 4);  // v4 v5
        float t = a.y + b.x;                    // v1+v2
        float u = b.y + c.x;                    // v3+v4
        float hl0 = a.x + t;                    // v0+v1+v2
        float hl1 = t + b.y;                    // v1+v2+v3
        float hr0 = b.x + u;                    // v2+v3+v4
        float hr1 = u + c.y;                    // v3+v4+v5
        hl = pk(hl0, hl1);
        hr = pk(hr0, hr1);
        cc = pk(b.x, b.y);                      // aligned pair straight from LDS.64
    };

    #pragma unroll
    for (int k = 0; k < 4; k++) loadrow(row0 + k, Hl[k], Hr[k], Cc[k]);

    // vertical 3-sum pipeline: V(t) = rows t..t+2.  A(p)=V(p), B(p)=V(p+2)=A(p+2)
    ull VHl[2], VHr[2], VHc[2];
    VHl[0] = add2(add2(Hl[0], Hl[1]), Hl[2]);
    VHr[0] = add2(add2(Hr[0], Hr[1]), Hr[2]);
    VHc[0] = add2(add2(Cc[0], Cc[1]), Cc[2]);
    VHl[1] = add2(add2(Hl[1], Hl[2]), Hl[3]);
    VHr[1] = add2(add2(Hr[1], Hr[2]), Hr[3]);
    VHc[1] = add2(add2(Cc[1], Cc[2]), Cc[3]);

    const ull K9    = 0x4110000041100000ULL;  // ( 9, 9)
    const ull Km9   = 0xC1100000C1100000ULL;  // (-9,-9)
    const ull K15   = 0x4170000041700000ULL;  // (15,15)
    const ull Km135 = 0xC3070000C3070000ULL;  // (-135,-135)
    const float INV135 = 1.0f / 135.0f;

    float* drow = dst + (by + row0) * IMG_W + bx + 2 * tx;

    #pragma unroll
    for (int p = 0; p < PY; p++) {
        const int s4 = (p + 4) % 5;
        loadrow(row0 + p + 4, Hl[s4], Hr[s4], Cc[s4]);
        const int i2 = (p + 2) % 5, i3 = (p + 3) % 5;

        ull Bl = add2(add2(Hl[i2], Hl[i3]), Hl[s4]);
        ull Br = add2(add2(Hr[i2], Hr[i3]), Hr[s4]);
        ull Bc = add2(add2(Cc[i2], Cc[i3]), Cc[s4]);
        ull Al = VHl[p & 1], Ar = VHr[p & 1], Ac = VHc[p & 1];
        VHl[p & 1] = Bl; VHr[p & 1] = Br; VHc[p & 1] = Bc;

        ull cc2  = Cc[i2];
        ull negC = mul2(cc2, Km135);
        ull hlc  = Hl[i2], hrc = Hr[i2];

        // residuals scaled by 135: e = 135*(conv - c); argmin|e| == argmin|d|
        ull eL  = fma2(hlc, Km9, fma2(add2(Al, Bl), K9, negC));
        ull eR  = fma2(hrc, Km9, fma2(add2(Ar, Br), K9, negC));
        ull eU  = fma2(Ac,  Km9, fma2(add2(Al, Ar), K9, negC));
        ull eD  = fma2(Bc,  Km9, fma2(add2(Bl, Br), K9, negC));
        ull eNW = fma2(Al, K15, negC);
        ull eNE = fma2(Ar, K15, negC);
        ull eSW = fma2(Bl, K15, negC);
        ull eSE = fma2(Br, K15, negC);

        float c0, c1;   upk(cc2, c0, c1);
        float l0, l1;   upk(eL,  l0, l1);
        float r0, r1;   upk(eR,  r0, r1);
        float u0, u1;   upk(eU,  u0, u1);
        float d0, d1;   upk(eD,  d0, d1);
        float nw0, nw1; upk(eNW, nw0, nw1);
        float ne0, ne1; upk(eNE, ne0, ne1);
        float sw0, sw1; upk(eSW, sw0, sw1);
        float se0, se1; upk(eSE, se0, se1);

        float m0 = selmin(selmin(selmin(l0, r0), selmin(u0, d0)),
                          selmin(selmin(nw0, ne0), selmin(sw0, se0)));
        float m1 = selmin(selmin(selmin(l1, r1), selmin(u1, d1)),
                          selmin(selmin(nw1, ne1), selmin(sw1, se1)));

        *(float2*)drow = make_float2(fmaf(m0, INV135, c0), fmaf(m1, INV135, c1));
        drow += IMG_W;
    }
}

// ---------------------------------------------------------------------------
// |x0 - res| clipped, CHW -> HWC (float4-vectorized, 4 pixels/thread)
// ---------------------------------------------------------------------------
__global__ void finalize_kernel(const float* __restrict__ img, float* __restrict__ out) {
    int p = blockIdx.x * blockDim.x + threadIdx.x;
    if (p >= HW / 4) return;
    const float4* in = (const float4*)img + 3 * p;
    float4 a = in[0], b = in[1], c = in[2];
    float4 r0 = ((const float4*)(g_bufA + 0 * HW))[p];
    float4 r1 = ((const float4*)(g_bufA + 1 * HW))[p];
    float4 r2 = ((const float4*)(g_bufA + 2 * HW))[p];
    float4 o0 = make_float4(fminf(fabsf(a.x - r0.x), 255.f), fminf(fabsf(a.y - r1.x), 255.f),
                            fminf(fabsf(a.z - r2.x), 255.f), fminf(fabsf(a.w - r0.y), 255.f));
    float4 o1 = make_float4(fminf(fabsf(b.x - r1.y), 255.f), fminf(fabsf(b.y - r2.y), 255.f),
                            fminf(fabsf(b.z - r0.z), 255.f), fminf(fabsf(b.w - r1.z), 255.f));
    float4 o2 = make_float4(fminf(fabsf(c.x - r2.z), 255.f), fminf(fabsf(c.y - r0.w), 255.f),
                            fminf(fabsf(c.z - r1.w), 255.f), fminf(fabsf(c.w - r2.w), 255.f));
    float4* op = (float4*)out + 3 * p;
    op[0] = o0; op[1] = o1; op[2] = o2;
}

// ---------------------------------------------------------------------------
extern "C" void kernel_launch(void* const* d_in, const int* in_sizes, int n_in,
                              void* d_out, int out_size) {
    const float* img = (const float*)d_in[0];
    float* out = (float*)d_out;

    hwc2chw_kernel<<<HW / 4 / 256, 256>>>(img);

    dim3 grid(IMG_W / TX, IMG_H / TY, NCH);
    dim3 block(32, 4);
    for (int it = 0; it < ITER; it++) {
        swf_step_kernel<<<grid, block>>>((it & 1) == 0 ? 1 : 0);
    }
    // After 8 iterations (even), result is back in g_bufA.
    finalize_kernel<<<HW / 4 / 256, 256>>>(img, out);
}

// round 5
// speedup vs baseline: 1.5775x; 1.0482x over previous
#include <cuda_runtime.h>

#define IMG_H 2048
#define IMG_W 2048
#define HW (IMG_H * IMG_W)
#define NCH 3
#define ITER 8

// Ping-pong scratch planes (CHW, planar). Device globals: allowed scratch.
__device__ float g_bufA[NCH * HW];
__device__ float g_bufB[NCH * HW];

typedef unsigned long long ull;

// ---------------- packed f32x2 helpers (Blackwell dual-FP32) ----------------
__device__ __forceinline__ ull pk(float lo, float hi) {
    ull r; asm("mov.b64 %0, {%1, %2};" : "=l"(r) : "f"(lo), "f"(hi)); return r;
}
__device__ __forceinline__ void upk(ull v, float& lo, float& hi) {
    asm("mov.b64 {%0, %1}, %2;" : "=f"(lo), "=f"(hi) : "l"(v));
}
__device__ __forceinline__ ull add2(ull a, ull b) {
    ull r; asm("add.rn.f32x2 %0, %1, %2;" : "=l"(r) : "l"(a), "l"(b)); return r;
}
__device__ __forceinline__ ull mul2(ull a, ull b) {
    ull r; asm("mul.rn.f32x2 %0, %1, %2;" : "=l"(r) : "l"(a), "l"(b)); return r;
}
__device__ __forceinline__ ull fma2(ull a, ull b, ull c) {
    ull r; asm("fma.rn.f32x2 %0, %1, %2, %3;" : "=l"(r) : "l"(a), "l"(b), "l"(c)); return r;
}
// keep `a` on tie (earlier kernel has priority) -> FSETP(|.|)+FSEL, 2 ops
__device__ __forceinline__ float selmin(float a, float b) {
    return (fabsf(b) < fabsf(a)) ? b : a;
}

// ---------------------------------------------------------------------------
// HWC -> CHW planar (float4-vectorized, 4 pixels/thread)
// ---------------------------------------------------------------------------
__global__ void hwc2chw_kernel(const float* __restrict__ img) {
    int p = blockIdx.x * blockDim.x + threadIdx.x;
    if (p >= HW / 4) return;
    const float4* in = (const float4*)img + 3 * p;
    float4 a = in[0], b = in[1], c = in[2];
    ((float4*)(g_bufA + 0 * HW))[p] = make_float4(a.x, a.w, b.z, c.y);
    ((float4*)(g_bufA + 1 * HW))[p] = make_float4(a.y, b.x, b.w, c.z);
    ((float4*)(g_bufA + 2 * HW))[p] = make_float4(a.z, b.y, c.x, c.w);
}

// ---------------------------------------------------------------------------
// One SWF iteration. Tile: 128 wide x 32 high per block (32,4)=128 threads.
// Each thread: 4 adjacent columns (two packed f32x2 streams) x 8 rows.
// Tile row layout: tc 0..3 pad, tc 4..5 left halo, tc 6..133 cols, 134..135 right halo.
// img col = bx + tc - 6.  Own cols c0..c3 = bx+4tx.. -> v0..v7 at tc 4tx+4..4tx+11,
// loaded as two aligned LDS.128 (byte addr 16(tx+1) and 16(tx+2): conflict-free).
// ---------------------------------------------------------------------------
#define TX 128
#define TY 32
#define PY 8
#define TROWS 36
#define STRIDE 136

__global__ __launch_bounds__(128) void swf_step_kernel(int srcIsA) {
    const float* __restrict__ src = (srcIsA ? g_bufA : g_bufB) + blockIdx.z * HW;
    float* __restrict__ dst       = (srcIsA ? g_bufB : g_bufA) + blockIdx.z * HW;

    __shared__ float tile[TROWS * STRIDE];

    const int tx = threadIdx.x, ty = threadIdx.y;
    const int bx = blockIdx.x * TX, by = blockIdx.y * TY;

    const bool interior = (blockIdx.x > 0) && (blockIdx.x < gridDim.x - 1) &&
                          (blockIdx.y > 0) && (blockIdx.y < gridDim.y - 1);

    if (interior) {
        const float* g = src + (by - 2) * IMG_W + (bx - 2);
        #pragma unroll
        for (int r = ty; r < TROWS; r += 4) {
            *(float2*)&tile[r * STRIDE + 4 + 2 * tx]   = *(const float2*)(g + r * IMG_W + 2 * tx);
            *(float2*)&tile[r * STRIDE + 68 + 2 * tx]  = *(const float2*)(g + r * IMG_W + 64 + 2 * tx);
            if (tx < 2)
                *(float2*)&tile[r * STRIDE + 132 + 2 * tx] = *(const float2*)(g + r * IMG_W + 128 + 2 * tx);
        }
    } else {
        #pragma unroll
        for (int r = ty; r < TROWS; r += 4) {
            int gy = min(max(by + r - 2, 0), IMG_H - 1);
            const float* grow = src + gy * IMG_W;
            #pragma unroll
            for (int k = 0; k < 2; k++) {
                int idx = tx + 32 * k;
                int c0 = min(max(bx - 2 + 2 * idx, 0), IMG_W - 1);
                int c1 = min(max(bx - 1 + 2 * idx, 0), IMG_W - 1);
                *(float2*)&tile[r * STRIDE + 4 + 2 * idx] = make_float2(grow[c0], grow[c1]);
            }
            if (tx < 2) {
                int idx = tx + 64;
                int c0 = min(max(bx - 2 + 2 * idx, 0), IMG_W - 1);
                int c1 = min(max(bx - 1 + 2 * idx, 0), IMG_W - 1);
                *(float2*)&tile[r * STRIDE + 4 + 2 * idx] = make_float2(grow[c0], grow[c1]);
            }
        }
    }
    __syncthreads();

    const int row0 = ty * PY;

    // Ring buffers (5 rows live): three shared horizontal 3-sum channels + 2 center pairs
    // h_i(row) = v_i+v_{i+1}+v_{i+2}; H0=(h0,h1) H1=(h2,h3) H2=(h4,h5); C0=(v2,v3) C1=(v4,v5)
    ull H0r[5], H1r[5], H2r[5], C0r[5], C1r[5];

    auto loadrow = [&](int r, ull& H0, ull& H1, ull& H2, ull& C0, ull& C1) {
        const float* base = &tile[r * STRIDE + 4 * tx + 4];
        float4 q0 = *(const float4*)(base);      // v0 v1 v2 v3
        float4 q1 = *(const float4*)(base + 4);  // v4 v5 v6 v7
        float s0 = q0.x + q0.y, s1 = q0.y + q0.z, s2 = q0.z + q0.w;
        float s3 = q0.w + q1.x, s4 = q1.x + q1.y, s5 = q1.y + q1.z;
        H0 = pk(s0 + q0.z, s1 + q0.w);
        H1 = pk(s2 + q1.x, s3 + q1.y);
        H2 = pk(s4 + q1.z, s5 + q1.w);
        C0 = pk(q0.z, q0.w);   // aligned pair of q0 quad
        C1 = pk(q1.x, q1.y);   // aligned pair of q1 quad
    };

    #pragma unroll
    for (int k = 0; k < 4; k++)
        loadrow(row0 + k, H0r[k], H1r[k], H2r[k], C0r[k], C1r[k]);

    const ull K9    = 0x4110000041100000ULL;  // ( 9, 9)
    const ull Km9   = 0xC1100000C1100000ULL;  // (-9,-9)
    const ull K15   = 0x4170000041700000ULL;  // (15,15)
    const ull Km135 = 0xC3070000C3070000ULL;  // (-135,-135)
    const float INV135 = 1.0f / 135.0f;

    float* drow = dst + (by + row0) * IMG_W + bx + 4 * tx;

    #pragma unroll
    for (int p = 0; p < PY; p++) {
        const int s4i = (p + 4) % 5;
        loadrow(row0 + p + 4, H0r[s4i], H1r[s4i], H2r[s4i], C0r[s4i], C1r[s4i]);
        const int i0 = p % 5, i1 = (p + 1) % 5, i2 = (p + 2) % 5, i3 = (p + 3) % 5;

        // vertical 3-sums: A = rows p..p+2, B = rows p+2..p+4
        ull A0 = add2(H0r[i0], add2(H0r[i1], H0r[i2]));
        ull B0 = add2(add2(H0r[i2], H0r[i3]), H0r[s4i]);
        ull A1 = add2(H1r[i0], add2(H1r[i1], H1r[i2]));
        ull B1 = add2(add2(H1r[i2], H1r[i3]), H1r[s4i]);
        ull A2 = add2(H2r[i0], add2(H2r[i1], H2r[i2]));
        ull B2 = add2(add2(H2r[i2], H2r[i3]), H2r[s4i]);
        ull Ac0 = add2(C0r[i0], add2(C0r[i1], C0r[i2]));
        ull Bc0 = add2(add2(C0r[i2], C0r[i3]), C0r[s4i]);
        ull Ac1 = add2(C1r[i0], add2(C1r[i1], C1r[i2]));
        ull Bc1 = add2(add2(C1r[i2], C1r[i3]), C1r[s4i]);

        float o[4];

        auto stream = [&](ull Al, ull Bl, ull Ar, ull Br, ull Ac, ull Bc,
                          ull Hlm, ull Hrm, ull ccm, float& oa, float& ob) {
            ull negC = mul2(ccm, Km135);
            // residuals scaled by 135: argmin|e| == argmin|d|
            ull eL  = fma2(Hlm, Km9, fma2(add2(Al, Bl), K9, negC));
            ull eR  = fma2(Hrm, Km9, fma2(add2(Ar, Br), K9, negC));
            ull eU  = fma2(Ac,  Km9, fma2(add2(Al, Ar), K9, negC));
            ull eD  = fma2(Bc,  Km9, fma2(add2(Bl, Br), K9, negC));
            ull eNW = fma2(Al, K15, negC);
            ull eNE = fma2(Ar, K15, negC);
            ull eSW = fma2(Bl, K15, negC);
            ull eSE = fma2(Br, K15, negC);

            float c0, c1;   upk(ccm, c0, c1);
            float l0, l1;   upk(eL,  l0, l1);
            float r0, r1;   upk(eR,  r0, r1);
            float u0, u1;   upk(eU,  u0, u1);
            float d0, d1;   upk(eD,  d0, d1);
            float nw0, nw1; upk(eNW, nw0, nw1);
            float ne0, ne1; upk(eNE, ne0, ne1);
            float sw0, sw1; upk(eSW, sw0, sw1);
            float se0, se1; upk(eSE, se0, se1);

            float m0 = selmin(selmin(selmin(l0, r0), selmin(u0, d0)),
                              selmin(selmin(nw0, ne0), selmin(sw0, se0)));
            float m1 = selmin(selmin(selmin(l1, r1), selmin(u1, d1)),
                              selmin(selmin(nw1, ne1), selmin(sw1, se1)));

            oa = fmaf(m0, INV135, c0);
            ob = fmaf(m1, INV135, c1);
        };

        // stream 0: cols c0,c1 (Hl=H0, Hr=H1, cc=C0); stream 1: cols c2,c3 (Hl=H1, Hr=H2, cc=C1)
        stream(A0, B0, A1, B1, Ac0, Bc0, H0r[i2], H1r[i2], C0r[i2], o[0], o[1]);
        stream(A1, B1, A2, B2, Ac1, Bc1, H1r[i2], H2r[i2], C1r[i2], o[2], o[3]);

        *(float4*)drow = make_float4(o[0], o[1], o[2], o[3]);
        drow += IMG_W;
    }
}

// ---------------------------------------------------------------------------
// |x0 - res| clipped, CHW -> HWC (float4-vectorized, 4 pixels/thread)
// ---------------------------------------------------------------------------
__global__ void finalize_kernel(const float* __restrict__ img, float* __restrict__ out) {
    int p = blockIdx.x * blockDim.x + threadIdx.x;
    if (p >= HW / 4) return;
    const float4* in = (const float4*)img + 3 * p;
    float4 a = in[0], b = in[1], c = in[2];
    float4 r0 = ((const float4*)(g_bufA + 0 * HW))[p];
    float4 r1 = ((const float4*)(g_bufA + 1 * HW))[p];
    float4 r2 = ((const float4*)(g_bufA + 2 * HW))[p];
    float4 o0 = make_float4(fminf(fabsf(a.x - r0.x), 255.f), fminf(fabsf(a.y - r1.x), 255.f),
                            fminf(fabsf(a.z - r2.x), 255.f), fminf(fabsf(a.w - r0.y), 255.f));
    float4 o1 = make_float4(fminf(fabsf(b.x - r1.y), 255.f), fminf(fabsf(b.y - r2.y), 255.f),
                            fminf(fabsf(b.z - r0.z), 255.f), fminf(fabsf(b.w - r1.z), 255.f));
    float4 o2 = make_float4(fminf(fabsf(c.x - r2.z), 255.f), fminf(fabsf(c.y - r0.w), 255.f),
                            fminf(fabsf(c.z - r1.w), 255.f), fminf(fabsf(c.w - r2.w), 255.f));
    float4* op = (float4*)out + 3 * p;
    op[0] = o0; op[1] = o1; op[2] = o2;
}

// ---------------------------------------------------------------------------
extern "C" void kernel_launch(void* const* d_in, const int* in_sizes, int n_in,
                              void* d_out, int out_size) {
    const float* img = (const float*)d_in[0];
    float* out = (float*)d_out;

    hwc2chw_kernel<<<HW / 4 / 256, 256>>>(img);

    dim3 grid(IMG_W / TX, IMG_H / TY, NCH);
    dim3 block(32, 4);
    for (int it = 0; it < ITER; it++) {
        swf_step_kernel<<<grid, block>>>((it & 1) == 0 ? 1 : 0);
    }
    // After 8 iterations (even), result is back in g_bufA.
    finalize_kernel<<<HW / 4 / 256, 256>>>(img, out);
}